// round 6
// baseline (speedup 1.0000x reference)
#include <cuda_runtime.h>

#define F 8
#define T 512
#define NN 512
#define NR 128
#define FT 4096
#define NW 1024          // F*NR, row width of t-major vectors
#define BS 32
#define NB 16
#define NITER 40

__device__ float g_K0[F * T * T];   // pristine K (for Newton)
__device__ float g_Kw[F * T * T];   // sweep workspace -> X0 (approx K_inv)
__device__ float g_Wn[F * T * T];   // Newton intermediate W = 2I - K*X0
__device__ float g_Sf[T * T];       // Ssum = sum_f K_inv_f
__device__ float g_Di[F * BS * BS];
__device__ float g_crinv[F * NN], g_crc[F * F], g_cd[F], g_invd[FT];
__device__ float g_B[FT * NR], g_X[FT * NR], g_Rv[FT * NR];
__device__ float g_Z[FT * NR], g_P[FT * NR], g_AP[FT * NR];
__device__ float g_pAp[256 * NR];
__device__ float g_zp[2][32 * NR];

// ---------- setup: crinv = C'R^-1, crc = C'R^-1 C, cd = C'R^-1 d ----------
__global__ void k_setup(const float* __restrict__ Cm, const float* __restrict__ dm,
                        const float* __restrict__ rd) {
    int tid = threadIdx.x;
    for (int i = tid; i < F * NN; i += 256) {
        int f = i / NN, n = i % NN;
        g_crinv[f * NN + n] = Cm[n * F + f] / rd[n];
    }
    __syncthreads();
    int w = tid >> 5, l = tid & 31;
    for (int q = 0; q < 8; q++) {
        int e = w * 8 + q, i = e / F, j = e % F;
        float s = 0.f;
        for (int n = l; n < NN; n += 32) s += g_crinv[i * NN + n] * Cm[n * F + j];
        for (int o = 16; o; o >>= 1) s += __shfl_xor_sync(0xffffffffu, s, o);
        if (l == 0) g_crc[e] = s;
    }
    {
        float s = 0.f;
        for (int n = l; n < NN; n += 32) s += g_crinv[w * NN + n] * dm[n];
        for (int o = 16; o; o >>= 1) s += __shfl_xor_sync(0xffffffffu, s, o);
        if (l == 0) g_cd[w] = s;
    }
}

// ---------- build K (fp32, matches reference arithmetic) ----------
__global__ void k_buildK(const float* __restrict__ gm) {
    int t = blockIdx.x, f = blockIdx.y;
    float g = gm[f];
    size_t base = ((size_t)f * T + t) * T;
    for (int u = threadIdx.x; u < T; u += blockDim.x) {
        float d = (float)(t - u);
        float v = (1.0f - 1e-3f) * expf(-0.5f * g * d * d);
        if (u == t) v += 1e-3f;
        g_K0[base + u] = v;
        g_Kw[base + u] = v;
    }
}

// ---------- blocked Gauss-Jordan sweep on g_Kw (fp32, BS=32) ----------
__global__ void k_diag(int k) {
    __shared__ float s[BS][BS + 1];
    int f = blockIdx.x, tid = threadIdx.x;
    float* A = g_Kw + (size_t)f * T * T;
    for (int i = tid; i < BS * BS; i += 256)
        s[i >> 5][i & 31] = A[(size_t)(k * BS + (i >> 5)) * T + k * BS + (i & 31)];
    __syncthreads();
    for (int p = 0; p < BS; p++) {
        float pv = 1.0f / s[p][p];
        for (int j = tid; j < BS; j += 256) if (j != p) s[p][j] *= pv;
        __syncthreads();
        for (int i = tid; i < BS * BS; i += 256) {
            int r = i >> 5, c = i & 31;
            if (r != p && c != p) s[r][c] -= s[r][p] * s[p][c];
        }
        __syncthreads();
        for (int i = tid; i < BS; i += 256) if (i != p) s[i][p] *= -pv;
        if (tid == 0) s[p][p] = pv;
        __syncthreads();
    }
    for (int i = tid; i < BS * BS; i += 256) g_Di[f * BS * BS + i] = s[i >> 5][i & 31];
}

__device__ __forceinline__ void mm32f(const float* sA, const float* sB,
                                      float acc[2][2], int ty, int tx) {
    for (int kk = 0; kk < BS; kk++) {
        float a0 = sA[(ty + 0) * 33 + kk], a1 = sA[(ty + 1) * 33 + kk];
        float b0 = sB[kk * 33 + tx + 0], b1 = sB[kk * 33 + tx + 1];
        acc[0][0] += a0 * b0; acc[0][1] += a0 * b1;
        acc[1][0] += a1 * b0; acc[1][1] += a1 * b1;
    }
}

__global__ void __launch_bounds__(256) k_row(int k) {
    int f = blockIdx.x, jb = blockIdx.y;
    if (jb == k) return;
    __shared__ float sD[BS * 33], sA[BS * 33];
    float* A = g_Kw + (size_t)f * T * T;
    int tid = threadIdx.x;
    for (int i = tid; i < BS * BS; i += 256) {
        sD[(i >> 5) * 33 + (i & 31)] = g_Di[f * BS * BS + i];
        sA[(i >> 5) * 33 + (i & 31)] = A[(size_t)(k * BS + (i >> 5)) * T + jb * BS + (i & 31)];
    }
    __syncthreads();
    int ty = (tid >> 4) << 1, tx = (tid & 15) << 1;
    float acc[2][2] = {};
    mm32f(sD, sA, acc, ty, tx);
    for (int i = 0; i < 2; i++)
        for (int j = 0; j < 2; j++)
            A[(size_t)(k * BS + ty + i) * T + jb * BS + tx + j] = acc[i][j];
}

__global__ void __launch_bounds__(256) k_int(int k) {
    int f = blockIdx.x, ib = blockIdx.y, jb = blockIdx.z;
    if (ib == k || jb == k) return;
    __shared__ float sA[BS * 33], sB[BS * 33];
    float* A = g_Kw + (size_t)f * T * T;
    int tid = threadIdx.x;
    for (int i = tid; i < BS * BS; i += 256) {
        sA[(i >> 5) * 33 + (i & 31)] = A[(size_t)(ib * BS + (i >> 5)) * T + k * BS + (i & 31)];
        sB[(i >> 5) * 33 + (i & 31)] = A[(size_t)(k * BS + (i >> 5)) * T + jb * BS + (i & 31)];
    }
    __syncthreads();
    int ty = (tid >> 4) << 1, tx = (tid & 15) << 1;
    float acc[2][2] = {};
    mm32f(sA, sB, acc, ty, tx);
    for (int i = 0; i < 2; i++)
        for (int j = 0; j < 2; j++) {
            size_t idx = (size_t)(ib * BS + ty + i) * T + jb * BS + tx + j;
            A[idx] = A[idx] - acc[i][j];
        }
}

__global__ void __launch_bounds__(256) k_col(int k) {
    int f = blockIdx.x, ib = blockIdx.y;
    float* A = g_Kw + (size_t)f * T * T;
    int tid = threadIdx.x;
    if (ib == k) {
        for (int i = tid; i < BS * BS; i += 256)
            A[(size_t)(k * BS + (i >> 5)) * T + k * BS + (i & 31)] = g_Di[f * BS * BS + i];
        return;
    }
    __shared__ float sA[BS * 33], sD[BS * 33];
    for (int i = tid; i < BS * BS; i += 256) {
        sA[(i >> 5) * 33 + (i & 31)] = A[(size_t)(ib * BS + (i >> 5)) * T + k * BS + (i & 31)];
        sD[(i >> 5) * 33 + (i & 31)] = g_Di[f * BS * BS + i];
    }
    __syncthreads();
    int ty = (tid >> 4) << 1, tx = (tid & 15) << 1;
    float acc[2][2] = {};
    mm32f(sA, sD, acc, ty, tx);
    for (int i = 0; i < 2; i++)
        for (int j = 0; j < 2; j++)
            A[(size_t)(ib * BS + ty + i) * T + k * BS + tx + j] = -acc[i][j];
}

// ---------- Newton refinement: which=0: Wn = 2I - K0*Kw ; which=1: K0 = Kw*Wn
__global__ void __launch_bounds__(256) k_gemm(int which) {
    int jb = blockIdx.x, ib = blockIdx.y, f = blockIdx.z;
    const float* A = (which ? g_Kw : g_K0) + (size_t)f * T * T;
    const float* Bm = (which ? g_Wn : g_Kw) + (size_t)f * T * T;
    float* C = (which ? g_K0 : g_Wn) + (size_t)f * T * T;
    __shared__ float sA[BS * 33], sB[BS * 33];
    int tid = threadIdx.x;
    int ty = (tid >> 4) << 1, tx = (tid & 15) << 1;
    float acc[2][2] = {};
    for (int kc = 0; kc < T; kc += BS) {
        __syncthreads();
        for (int i = tid; i < BS * BS; i += 256) {
            sA[(i >> 5) * 33 + (i & 31)] = A[(size_t)(ib * BS + (i >> 5)) * T + kc + (i & 31)];
            sB[(i >> 5) * 33 + (i & 31)] = Bm[(size_t)(kc + (i >> 5)) * T + jb * BS + (i & 31)];
        }
        __syncthreads();
        mm32f(sA, sB, acc, ty, tx);
    }
    for (int i = 0; i < 2; i++)
        for (int j = 0; j < 2; j++) {
            int row = ib * BS + ty + i, col = jb * BS + tx + j;
            float v = which ? acc[i][j] : ((row == col ? 2.f : 0.f) - acc[i][j]);
            C[(size_t)row * T + col] = v;
        }
}

// Ssum = sum_f K_inv_f  (K_inv now in g_K0)
__global__ void k_sum() {
    int i = blockIdx.x * 256 + threadIdx.x;
    if (i >= T * T) return;
    float s = 0.f;
#pragma unroll
    for (int f = 0; f < F; f++) s += g_K0[(size_t)f * T * T + i];
    g_Sf[i] = s;
}

// Jacobi preconditioner: row = t*F+f -> 1/(Ssum[t,t] + crc[f,f])
__global__ void k_invd() {
    int i = blockIdx.x * 256 + threadIdx.x;
    if (i >= FT) return;
    int t = i >> 3, f = i & 7;
    g_invd[i] = 1.0f / (g_Sf[(size_t)t * T + t] + g_crc[f * F + f]);
}

// B[(t*F+f)*NR + r] = sum_n crinv[f,n]*spike[r,n,t] - cd[f]
__global__ void __launch_bounds__(128) k_term1(const float* __restrict__ sp) {
    int r = blockIdx.x, tid = threadIdx.x;
    __shared__ float sc[F][NN];
    __shared__ float scd[F];
    for (int i = tid; i < F * NN; i += 128) sc[i / NN][i % NN] = g_crinv[i];
    if (tid < F) scd[tid] = g_cd[tid];
    __syncthreads();
    float ax[F], ay[F], az[F], aw[F];
#pragma unroll
    for (int f = 0; f < F; f++) { ax[f] = ay[f] = az[f] = aw[f] = 0.f; }
    const float4* S = (const float4*)(sp + (size_t)r * NN * T);
#pragma unroll 2
    for (int n = 0; n < NN; n++) {
        float4 v = S[n * (T / 4) + tid];
#pragma unroll
        for (int f = 0; f < F; f++) {
            float c = sc[f][n];
            ax[f] += c * v.x; ay[f] += c * v.y; az[f] += c * v.z; aw[f] += c * v.w;
        }
    }
    int t0 = tid * 4;
#pragma unroll
    for (int f = 0; f < F; f++) {
        g_B[((size_t)(t0 + 0) * F + f) * NR + r] = ax[f] - scd[f];
        g_B[((size_t)(t0 + 1) * F + f) * NR + r] = ay[f] - scd[f];
        g_B[((size_t)(t0 + 2) * F + f) * NR + r] = az[f] - scd[f];
        g_B[((size_t)(t0 + 3) * F + f) * NR + r] = aw[f] - scd[f];
    }
}

__global__ void k_cginit() {
    int b = blockIdx.x, r = threadIdx.x;   // 32 x 128
    float part = 0.f;
    for (int i = 0; i < 128; i++) {
        int row = b * 128 + i;
        size_t idx = (size_t)row * NR + r;
        float bv = g_B[idx];
        float z = bv * g_invd[row];
        g_X[idx] = 0.f; g_Rv[idx] = bv; g_Z[idx] = z; g_P[idx] = z;
        part += z * bv;
    }
    g_zp[0][b * NR + r] = part;
}

// AP[t,(f,r)] = sum_u Ssum[t,u] P[u,(f,r)] + sum_g crc[f,g] P[t,(g,r)]
__global__ void __launch_bounds__(256) k_matvec() {
    int fb = blockIdx.x, tb = blockIdx.y, t0 = tb * 16;
    __shared__ float sS[16][33];
    __shared__ float sP[32][128];
    __shared__ float scrc[F];
    __shared__ float sred[8][128];
    int tid = threadIdx.x;
    if (tid < F) scrc[tid] = g_crc[fb * F + tid];
    int ty = tid >> 5, tx = tid & 31;
    float4 acc0 = make_float4(0.f, 0.f, 0.f, 0.f), acc1 = acc0;
    for (int uc = 0; uc < T; uc += 32) {
        __syncthreads();
        for (int i = tid; i < 16 * 32; i += 256)
            sS[i >> 5][i & 31] = g_Sf[(size_t)(t0 + (i >> 5)) * T + uc + (i & 31)];
        for (int i = tid; i < 32 * 32; i += 256)
            ((float4*)sP[i >> 5])[i & 31] =
                ((const float4*)(g_P + (size_t)(uc + (i >> 5)) * NW + fb * NR))[i & 31];
        __syncthreads();
#pragma unroll 8
        for (int uu = 0; uu < 32; uu++) {
            float4 pv = ((const float4*)sP[uu])[tx];
            float k0 = sS[ty * 2][uu], k1 = sS[ty * 2 + 1][uu];
            acc0.x += k0 * pv.x; acc0.y += k0 * pv.y;
            acc0.z += k0 * pv.z; acc0.w += k0 * pv.w;
            acc1.x += k1 * pv.x; acc1.y += k1 * pv.y;
            acc1.z += k1 * pv.z; acc1.w += k1 * pv.w;
        }
    }
    float4 pf0 = make_float4(0.f, 0.f, 0.f, 0.f), pf1 = pf0;
#pragma unroll
    for (int g = 0; g < F; g++) {
        float c = scrc[g];
        float4 q0 = ((const float4*)(g_P + (size_t)(t0 + ty * 2 + 0) * NW + g * NR))[tx];
        float4 q1 = ((const float4*)(g_P + (size_t)(t0 + ty * 2 + 1) * NW + g * NR))[tx];
        if (g == fb) { pf0 = q0; pf1 = q1; }
        acc0.x += c * q0.x; acc0.y += c * q0.y; acc0.z += c * q0.z; acc0.w += c * q0.w;
        acc1.x += c * q1.x; acc1.y += c * q1.y; acc1.z += c * q1.z; acc1.w += c * q1.w;
    }
    ((float4*)(g_AP + (size_t)(t0 + ty * 2 + 0) * NW + fb * NR))[tx] = acc0;
    ((float4*)(g_AP + (size_t)(t0 + ty * 2 + 1) * NW + fb * NR))[tx] = acc1;
    sred[ty][tx * 4 + 0] = pf0.x * acc0.x + pf1.x * acc1.x;
    sred[ty][tx * 4 + 1] = pf0.y * acc0.y + pf1.y * acc1.y;
    sred[ty][tx * 4 + 2] = pf0.z * acc0.z + pf1.z * acc1.z;
    sred[ty][tx * 4 + 3] = pf0.w * acc0.w + pf1.w * acc1.w;
    __syncthreads();
    if (tid < NR) {
        float s = 0.f;
#pragma unroll
        for (int w = 0; w < 8; w++) s += sred[w][tid];
        g_pAp[(fb * 32 + tb) * NR + tid] = s;
    }
}

__global__ void k_update(int par) {
    int b = blockIdx.x, r = threadIdx.x;  // 128 x 128
    float rho = 0.f, pap = 0.f;
    for (int j = 0; j < 32; j++) rho += g_zp[par][j * NR + r];
    for (int j = 0; j < 256; j++) pap += g_pAp[j * NR + r];
    float al = rho / pap;
    size_t base = (size_t)b * 32 * NR + r;
#pragma unroll 4
    for (int i = 0; i < 32; i++) {
        size_t idx = base + (size_t)i * NR;
        g_X[idx] += al * g_P[idx];
        g_Rv[idx] -= al * g_AP[idx];
    }
}

__global__ void k_z(int par) {
    int b = blockIdx.x, r = threadIdx.x;  // 32 x 128
    float part = 0.f;
    for (int i = 0; i < 128; i++) {
        int row = b * 128 + i;
        size_t idx = (size_t)row * NR + r;
        float rv = g_Rv[idx];
        float z = rv * g_invd[row];
        g_Z[idx] = z;
        part += z * rv;
    }
    g_zp[par ^ 1][b * NR + r] = part;
}

__global__ void k_pup(int par) {
    int b = blockIdx.x, r = threadIdx.x;  // 128 x 128
    float rn = 0.f, ro = 0.f;
    for (int j = 0; j < 32; j++) { rn += g_zp[par ^ 1][j * NR + r]; ro += g_zp[par][j * NR + r]; }
    float be = rn / ro;
    size_t base = (size_t)b * 32 * NR + r;
#pragma unroll 4
    for (int i = 0; i < 32; i++) {
        size_t idx = base + (size_t)i * NR;
        g_P[idx] = g_Z[idx] + be * g_P[idx];
    }
}

// out[r, f, t] = X[(t*F+f), r]
__global__ void k_out(float* __restrict__ out) {
    __shared__ float s[32][129];
    int base = blockIdx.x * 32, tid = threadIdx.x;
    for (int i = tid; i < 32 * NR; i += 256)
        s[i >> 7][i & 127] = g_X[(size_t)(base + (i >> 7)) * NR + (i & 127)];
    __syncthreads();
    for (int i = tid; i < 32 * NR; i += 256) {
        int r = i >> 5, row = i & 31, grow = base + row;
        int t = grow >> 3, f = grow & 7;
        out[(size_t)r * FT + f * T + t] = s[row][r];
    }
}

extern "C" void kernel_launch(void* const* d_in, const int* in_sizes, int n_in,
                              void* d_out, int out_size) {
    const float* sp = (const float*)d_in[0];
    const float* Cm = (const float*)d_in[1];
    const float* dm = (const float*)d_in[2];
    const float* rd = (const float*)d_in[3];
    const float* gm = (const float*)d_in[4];
    float* out = (float*)d_out;

    k_setup<<<1, 256>>>(Cm, dm, rd);
    k_buildK<<<dim3(T, F), 128>>>(gm);
    for (int k = 0; k < NB; k++) {
        k_diag<<<F, 256>>>(k);
        k_row<<<dim3(F, NB), 256>>>(k);
        k_int<<<dim3(F, NB, NB), 256>>>(k);
        k_col<<<dim3(F, NB), 256>>>(k);
    }
    k_gemm<<<dim3(16, 16, F), 256>>>(0);   // Wn = 2I - K0*X0
    k_gemm<<<dim3(16, 16, F), 256>>>(1);   // K0 = X0*Wn  (refined K_inv)
    k_sum<<<(T * T + 255) / 256, 256>>>();
    k_invd<<<FT / 256, 256>>>();
    k_term1<<<NR, 128>>>(sp);
    k_cginit<<<32, 128>>>();
    for (int it = 0; it < NITER; it++) {
        int par = it & 1;
        k_matvec<<<dim3(F, 32), 256>>>();
        k_update<<<128, 128>>>(par);
        if (it < NITER - 1) {
            k_z<<<32, 128>>>(par);
            k_pup<<<128, 128>>>(par);
        }
    }
    k_out<<<FT / 32, 256>>>(out);
}